// round 1
// baseline (speedup 1.0000x reference)
#include <cuda_runtime.h>
#include <cuda_bf16.h>
#include <stdint.h>

#define SEQ 80
#define EMB 100
#define VOCAB 10000
#define WSTRIDE 72   // padded bf16 row stride for conflict-free B-fragment LDS

// Precomputed emb @ Wx0 : [VOCAB, 64] fp32 (2.56 MB, lives in L2)
__device__ float g_embW0[VOCAB * 64];

// ---------------------------------------------------------------------------
// Kernel 1: embW0[v][j] = sum_k emb[v][k] * Wx0[k][j]
// grid = VOCAB/16 blocks, 256 threads (4 vocab rows x 64 units per pass)
// ---------------------------------------------------------------------------
__global__ void __launch_bounds__(256) embw0_kernel(const float* __restrict__ emb,
                                                    const float* __restrict__ Wx0) {
    __shared__ float sW[EMB * 64];
    __shared__ float sE[4][EMB];
    int tid = threadIdx.x;
    for (int i = tid; i < EMB * 64; i += 256) sW[i] = Wx0[i];
    int j  = tid & 63;
    int vs = tid >> 6;
    int vbase = blockIdx.x * 16;
    for (int it = 0; it < 4; ++it) {
        int v0 = vbase + it * 4;
        __syncthreads();
        for (int i = tid; i < 4 * EMB; i += 256)
            sE[i / EMB][i % EMB] = emb[(v0 + i / EMB) * EMB + (i % EMB)];
        __syncthreads();
        float a = 0.f;
        #pragma unroll
        for (int k = 0; k < EMB; ++k) a += sE[vs][k] * sW[k * 64 + j];
        g_embW0[(v0 + vs) * 64 + j] = a;
    }
}

// ---------------------------------------------------------------------------
// mma.m16n8k16 bf16 (row.col), fp32 accumulate, C==D in place
// ---------------------------------------------------------------------------
__device__ __forceinline__ void mma16816(float& d0, float& d1, float& d2, float& d3,
                                         uint32_t a0, uint32_t a1, uint32_t a2, uint32_t a3,
                                         uint32_t b0, uint32_t b1) {
    asm("mma.sync.aligned.m16n8k16.row.col.f32.bf16.bf16.f32 "
        "{%0,%1,%2,%3},{%4,%5,%6,%7},{%8,%9},{%0,%1,%2,%3};"
        : "+f"(d0), "+f"(d1), "+f"(d2), "+f"(d3)
        : "r"(a0), "r"(a1), "r"(a2), "r"(a3), "r"(b0), "r"(b1));
}

// pack(lo, hi): lo -> low 16 bits, hi -> high 16 bits
__device__ __forceinline__ uint32_t packbf(float lo, float hi) {
    uint32_t r;
    asm("cvt.rn.bf16x2.f32 %0, %1, %2;" : "=r"(r) : "f"(hi), "f"(lo));
    return r;
}

__device__ __forceinline__ float fast_tanh(float x) {
    float y;
    asm("tanh.approx.f32 %0, %1;" : "=f"(y) : "f"(x));
    return y;
}

// ---------------------------------------------------------------------------
// Kernel 2: the recurrence. 128 threads/CTA = 4 warps, warp handles M=32 rows.
// h0/h1 held in registers as bf16 A-fragments; acc is the fp32 D-fragment.
// D-fragment (2 adjacent n-tiles) == A-fragment layout -> no shuffles.
// ---------------------------------------------------------------------------
__global__ void __launch_bounds__(128, 1) rnn_kernel(
    const int*   __restrict__ tokens,
    const float* __restrict__ Wh0,
    const float* __restrict__ b0,
    const float* __restrict__ Wx1,
    const float* __restrict__ Wh1,
    const float* __restrict__ b1,
    const float* __restrict__ Wout,
    const float* __restrict__ bout,
    float*       __restrict__ out,
    int B) {
    // weights transposed to [n][k], bf16, padded stride 72 (conflict-free)
    __shared__ __align__(16) uint16_t sWall[3 * 64 * WSTRIDE];
    uint16_t* sW0 = sWall;                    // Wh0^T
    uint16_t* sW1 = sWall + 64 * WSTRIDE;     // Wx1^T
    uint16_t* sW2 = sWall + 2 * 64 * WSTRIDE; // Wh1^T

    {
        const float* Ws[3] = {Wh0, Wx1, Wh1};
        #pragma unroll
        for (int w = 0; w < 3; ++w) {
            for (int i = threadIdx.x; i < 64 * 64; i += 128) {
                int k = i >> 6, n = i & 63;
                __nv_bfloat16 v = __float2bfloat16(Ws[w][i]);
                sWall[w * 64 * WSTRIDE + n * WSTRIDE + k] =
                    *reinterpret_cast<uint16_t*>(&v);
            }
        }
    }
    __syncthreads();

    const int lane = threadIdx.x & 31;
    const int warp = threadIdx.x >> 5;
    const int g  = lane >> 2;   // groupID (row within tile)
    const int tq = lane & 3;    // thread-in-group (column pair selector)
    const int base = (blockIdx.x * 4 + warp) * 32;

    int rraw[4], rc[4];
    #pragma unroll
    for (int i = 0; i < 4; ++i) {
        rraw[i] = base + g + 8 * i;
        rc[i]   = rraw[i] < B ? rraw[i] : (B - 1);
    }

    // per-thread bias fragments (col = nt*8 + 2*tq + e)
    float b0f[16], b1f[16];
    #pragma unroll
    for (int nt = 0; nt < 8; ++nt) {
        b0f[nt * 2]     = b0[nt * 8 + tq * 2];
        b0f[nt * 2 + 1] = b0[nt * 8 + tq * 2 + 1];
        b1f[nt * 2]     = b1[nt * 8 + tq * 2];
        b1f[nt * 2 + 1] = b1[nt * 8 + tq * 2 + 1];
    }

    float    acc[64];    // D fragments: [i(0..3)][nt(0..7)][e(0..1)]
    uint32_t h0f[32];    // A fragments: [mt(0..1)][k(0..3)][q(0..3)]
    uint32_t h1f[32];
    #pragma unroll
    for (int i = 0; i < 32; ++i) { h0f[i] = 0u; h1f[i] = 0u; }

    // token prefetch (one step ahead)
    int tk[4];
    #pragma unroll
    for (int i = 0; i < 4; ++i) tk[i] = tokens[rc[i] * SEQ];

    #pragma unroll 1
    for (int ts = 0; ts < SEQ; ++ts) {
        int tkn[4];
        int tsn = (ts + 1 < SEQ) ? ts + 1 : ts;
        #pragma unroll
        for (int i = 0; i < 4; ++i) tkn[i] = tokens[rc[i] * SEQ + tsn];

        // ---- gather xW0 row + bias -> acc (fp32) ----
        #pragma unroll
        for (int i = 0; i < 4; ++i) {
            const float2* src =
                reinterpret_cast<const float2*>(g_embW0 + tk[i] * 64 + tq * 2);
            #pragma unroll
            for (int nt = 0; nt < 8; ++nt) {
                float2 v = src[nt * 4];
                acc[i * 16 + nt * 2]     = v.x + b0f[nt * 2];
                acc[i * 16 + nt * 2 + 1] = v.y + b0f[nt * 2 + 1];
            }
        }

        // ---- layer 0: acc += h0 @ Wh0 ----
        // n-tile pairs outer so early n-tiles start while late gathers land
        #pragma unroll
        for (int ntp = 0; ntp < 4; ++ntp) {
            #pragma unroll
            for (int k = 0; k < 4; ++k) {
                #pragma unroll
                for (int u = 0; u < 2; ++u) {
                    int nt = ntp * 2 + u;
                    const uint32_t* bp = reinterpret_cast<const uint32_t*>(
                        &sW0[(nt * 8 + g) * WSTRIDE + k * 16 + tq * 2]);
                    uint32_t w0 = bp[0], w1 = bp[4];
                    mma16816(acc[nt*2], acc[nt*2+1], acc[16+nt*2], acc[16+nt*2+1],
                             h0f[k*4+0], h0f[k*4+1], h0f[k*4+2], h0f[k*4+3], w0, w1);
                    mma16816(acc[32+nt*2], acc[32+nt*2+1], acc[48+nt*2], acc[48+nt*2+1],
                             h0f[16+k*4+0], h0f[16+k*4+1], h0f[16+k*4+2], h0f[16+k*4+3],
                             w0, w1);
                }
            }
        }

        // ---- tanh + pack -> new h0 fragments ----
        #pragma unroll
        for (int mt = 0; mt < 2; ++mt) {
            #pragma unroll
            for (int k = 0; k < 4; ++k) {
                int blo = (2 * mt) * 16, bhi = (2 * mt + 1) * 16;
                int c0 = (2 * k) * 2, c1 = (2 * k + 1) * 2;
                h0f[mt*16 + k*4 + 0] = packbf(fast_tanh(acc[blo + c0]), fast_tanh(acc[blo + c0 + 1]));
                h0f[mt*16 + k*4 + 1] = packbf(fast_tanh(acc[bhi + c0]), fast_tanh(acc[bhi + c0 + 1]));
                h0f[mt*16 + k*4 + 2] = packbf(fast_tanh(acc[blo + c1]), fast_tanh(acc[blo + c1 + 1]));
                h0f[mt*16 + k*4 + 3] = packbf(fast_tanh(acc[bhi + c1]), fast_tanh(acc[bhi + c1 + 1]));
            }
        }

        // ---- layer 1: acc = b1 + h0n @ Wx1 + h1 @ Wh1 ----
        #pragma unroll
        for (int i = 0; i < 4; ++i)
            #pragma unroll
            for (int e = 0; e < 16; ++e) acc[i * 16 + e] = b1f[e];

        #pragma unroll
        for (int k = 0; k < 4; ++k) {
            #pragma unroll
            for (int nt = 0; nt < 8; ++nt) {
                const uint32_t* bp = reinterpret_cast<const uint32_t*>(
                    &sW1[(nt * 8 + g) * WSTRIDE + k * 16 + tq * 2]);
                uint32_t w0 = bp[0], w1 = bp[4];
                mma16816(acc[nt*2], acc[nt*2+1], acc[16+nt*2], acc[16+nt*2+1],
                         h0f[k*4+0], h0f[k*4+1], h0f[k*4+2], h0f[k*4+3], w0, w1);
                mma16816(acc[32+nt*2], acc[32+nt*2+1], acc[48+nt*2], acc[48+nt*2+1],
                         h0f[16+k*4+0], h0f[16+k*4+1], h0f[16+k*4+2], h0f[16+k*4+3],
                         w0, w1);
            }
        }
        #pragma unroll
        for (int k = 0; k < 4; ++k) {
            #pragma unroll
            for (int nt = 0; nt < 8; ++nt) {
                const uint32_t* bp = reinterpret_cast<const uint32_t*>(
                    &sW2[(nt * 8 + g) * WSTRIDE + k * 16 + tq * 2]);
                uint32_t w0 = bp[0], w1 = bp[4];
                mma16816(acc[nt*2], acc[nt*2+1], acc[16+nt*2], acc[16+nt*2+1],
                         h1f[k*4+0], h1f[k*4+1], h1f[k*4+2], h1f[k*4+3], w0, w1);
                mma16816(acc[32+nt*2], acc[32+nt*2+1], acc[48+nt*2], acc[48+nt*2+1],
                         h1f[16+k*4+0], h1f[16+k*4+1], h1f[16+k*4+2], h1f[16+k*4+3],
                         w0, w1);
            }
        }

        // ---- tanh + pack -> new h1 fragments ----
        #pragma unroll
        for (int mt = 0; mt < 2; ++mt) {
            #pragma unroll
            for (int k = 0; k < 4; ++k) {
                int blo = (2 * mt) * 16, bhi = (2 * mt + 1) * 16;
                int c0 = (2 * k) * 2, c1 = (2 * k + 1) * 2;
                h1f[mt*16 + k*4 + 0] = packbf(fast_tanh(acc[blo + c0]), fast_tanh(acc[blo + c0 + 1]));
                h1f[mt*16 + k*4 + 1] = packbf(fast_tanh(acc[bhi + c0]), fast_tanh(acc[bhi + c0 + 1]));
                h1f[mt*16 + k*4 + 2] = packbf(fast_tanh(acc[blo + c1]), fast_tanh(acc[blo + c1 + 1]));
                h1f[mt*16 + k*4 + 3] = packbf(fast_tanh(acc[bhi + c1]), fast_tanh(acc[bhi + c1 + 1]));
            }
        }

        #pragma unroll
        for (int i = 0; i < 4; ++i) tk[i] = tkn[i];
    }

    // ---- output head: sigmoid(tanh(acc) @ Wout + bout) ----
    // acc still holds the final pre-activation of layer 1 (fp32)
    float wo[16];
    #pragma unroll
    for (int nt = 0; nt < 8; ++nt) {
        float2 v = *reinterpret_cast<const float2*>(Wout + nt * 8 + tq * 2);
        wo[nt * 2] = v.x; wo[nt * 2 + 1] = v.y;
    }
    float bo = bout[0];
    #pragma unroll
    for (int i = 0; i < 4; ++i) {
        float s = 0.f;
        #pragma unroll
        for (int nt = 0; nt < 8; ++nt) {
            s += fast_tanh(acc[i * 16 + nt * 2])     * wo[nt * 2];
            s += fast_tanh(acc[i * 16 + nt * 2 + 1]) * wo[nt * 2 + 1];
        }
        s += __shfl_xor_sync(0xffffffffu, s, 1);
        s += __shfl_xor_sync(0xffffffffu, s, 2);
        if (tq == 0 && rraw[i] < B)
            out[rraw[i]] = 1.0f / (1.0f + __expf(-(s + bo)));
    }
}

// ---------------------------------------------------------------------------
extern "C" void kernel_launch(void* const* d_in, const int* in_sizes, int n_in,
                              void* d_out, int out_size) {
    const int*   tokens = (const int*)  d_in[0];
    const float* emb    = (const float*)d_in[1];
    const float* Wx0    = (const float*)d_in[2];
    const float* Wh0    = (const float*)d_in[3];
    const float* b0     = (const float*)d_in[4];
    const float* Wx1    = (const float*)d_in[5];
    const float* Wh1    = (const float*)d_in[6];
    const float* b1     = (const float*)d_in[7];
    const float* Wout   = (const float*)d_in[8];
    const float* bout   = (const float*)d_in[9];
    float* out = (float*)d_out;

    int B = in_sizes[0] / SEQ;

    embw0_kernel<<<VOCAB / 16, 256>>>(emb, Wx0);

    int nblocks = (B + 127) / 128;
    rnn_kernel<<<nblocks, 128>>>(tokens, Wh0, b0, Wx1, Wh1, b1, Wout, bout, out, B);
}

// round 2
// speedup vs baseline: 2.3989x; 2.3989x over previous
#include <cuda_runtime.h>
#include <cuda_bf16.h>
#include <stdint.h>

#define SEQ 80
#define EMB 100
#define VOCAB 10000
#define BMAX 16384
#define WSTRIDE 72   // padded bf16 row stride: ldmatrix rows land on distinct 16B banks

// Precomputed emb @ Wx0 + b0 : [VOCAB, 64] fp32 (2.56 MB, L2-resident)
__device__ float g_embW0[VOCAB * 64];
// Transposed tokens [SEQ][B] for coalesced per-step loads
__device__ int g_tokT[SEQ * BMAX];

// ---------------------------------------------------------------------------
// Kernel 1: embW0[v][j] = sum_k emb[v][k] * Wx0[k][j] + b0[j]
// ---------------------------------------------------------------------------
__global__ void __launch_bounds__(256) embw0_kernel(const float* __restrict__ emb,
                                                    const float* __restrict__ Wx0,
                                                    const float* __restrict__ b0) {
    __shared__ float sW[EMB * 64];
    __shared__ float sE[4][EMB];
    int tid = threadIdx.x;
    for (int i = tid; i < EMB * 64; i += 256) sW[i] = Wx0[i];
    int j  = tid & 63;
    int vs = tid >> 6;
    int vbase = blockIdx.x * 16;
    float bj = b0[j];
    for (int it = 0; it < 4; ++it) {
        int v0 = vbase + it * 4;
        __syncthreads();
        for (int i = tid; i < 4 * EMB; i += 256)
            sE[i / EMB][i % EMB] = emb[(v0 + i / EMB) * EMB + (i % EMB)];
        __syncthreads();
        float a = bj;
        #pragma unroll
        for (int k = 0; k < EMB; ++k) a += sE[vs][k] * sW[k * 64 + j];
        g_embW0[(v0 + vs) * 64 + j] = a;
    }
}

// ---------------------------------------------------------------------------
// Kernel 1b: token transpose [B][SEQ] -> [SEQ][B] (coalesced writes)
// ---------------------------------------------------------------------------
__global__ void __launch_bounds__(256) tok_transpose(const int* __restrict__ tokens, int B) {
    int b = blockIdx.x * 256 + threadIdx.x;
    if (b < B) {
        #pragma unroll
        for (int s = 0; s < SEQ; ++s)
            g_tokT[s * B + b] = tokens[b * SEQ + s];
    }
}

// ---------------------------------------------------------------------------
// PTX helpers
// ---------------------------------------------------------------------------
__device__ __forceinline__ void mma16816(float& d0, float& d1, float& d2, float& d3,
                                         uint32_t a0, uint32_t a1, uint32_t a2, uint32_t a3,
                                         uint32_t b0, uint32_t b1) {
    asm("mma.sync.aligned.m16n8k16.row.col.f32.bf16.bf16.f32 "
        "{%0,%1,%2,%3},{%4,%5,%6,%7},{%8,%9},{%0,%1,%2,%3};"
        : "+f"(d0), "+f"(d1), "+f"(d2), "+f"(d3)
        : "r"(a0), "r"(a1), "r"(a2), "r"(a3), "r"(b0), "r"(b1));
}

__device__ __forceinline__ void ldsm4(uint32_t& x, uint32_t& y, uint32_t& z, uint32_t& w,
                                      uint32_t saddr) {
    asm volatile("ldmatrix.sync.aligned.m8n8.x4.shared.b16 {%0,%1,%2,%3}, [%4];"
                 : "=r"(x), "=r"(y), "=r"(z), "=r"(w) : "r"(saddr));
}

// pack(lo, hi): lo -> low 16 bits
__device__ __forceinline__ uint32_t packbf(float lo, float hi) {
    uint32_t r;
    asm("cvt.rn.bf16x2.f32 %0, %1, %2;" : "=r"(r) : "f"(hi), "f"(lo));
    return r;
}

__device__ __forceinline__ uint32_t tanh_bf16x2(uint32_t v) {
    uint32_t r;
    asm("tanh.approx.bf16x2 %0, %1;" : "=r"(r) : "r"(v));
    return r;
}

__device__ __forceinline__ float fast_tanh(float x) {
    float y;
    asm("tanh.approx.f32 %0, %1;" : "=f"(y) : "f"(x));
    return y;
}

// ---------------------------------------------------------------------------
// Kernel 2: recurrence. 4 warps/CTA, M=16 rows per warp, grid = B/64 = 256.
// accA/accB fp32 D-fragments; h0f/h1f bf16 A-fragments (D->A identity, no shfl).
// ---------------------------------------------------------------------------
__global__ void __launch_bounds__(128, 2) rnn_kernel(
    const float* __restrict__ Wh0,
    const float* __restrict__ Wx1,
    const float* __restrict__ Wh1,
    const float* __restrict__ b1,
    const float* __restrict__ Wout,
    const float* __restrict__ bout,
    float*       __restrict__ out,
    int B) {
    __shared__ __align__(16) uint16_t sWall[3 * 64 * WSTRIDE]; // Wh0^T, Wx1^T, Wh1^T
    __shared__ float sB1[64];

    {
        const float* Ws[3] = {Wh0, Wx1, Wh1};
        #pragma unroll
        for (int w = 0; w < 3; ++w) {
            for (int i = threadIdx.x; i < 64 * 64; i += 128) {
                int k = i >> 6, n = i & 63;
                __nv_bfloat16 v = __float2bfloat16(Ws[w][i]);
                sWall[w * 64 * WSTRIDE + n * WSTRIDE + k] =
                    *reinterpret_cast<uint16_t*>(&v);
            }
        }
        if (threadIdx.x < 64) sB1[threadIdx.x] = b1[threadIdx.x];
    }
    __syncthreads();

    const int lane = threadIdx.x & 31;
    const int warp = threadIdx.x >> 5;
    const int g  = lane >> 2;   // row-in-tile
    const int tq = lane & 3;    // column pair
    const int base = (blockIdx.x * 4 + warp) * 16;

    int rraw[2], rc[2];
    #pragma unroll
    for (int i = 0; i < 2; ++i) {
        rraw[i] = base + g + 8 * i;
        rc[i]   = rraw[i] < B ? rraw[i] : (B - 1);
    }

    // ldmatrix lane address offsets (halves): matrix j rows r
    const int laneoff = (lane & 7) * WSTRIDE + (lane >> 3) * 8;
    uint32_t swb = (uint32_t)__cvta_generic_to_shared(sWall);
    uint32_t aW0 = swb + 2 * laneoff;                  // Wh0^T
    uint32_t aW1 = aW0 + 2 * (64 * WSTRIDE);           // Wx1^T
    uint32_t aW2 = aW1 + 2 * (64 * WSTRIDE);           // Wh1^T

    float    accA[32];   // layer-0 pre-act / gather: [i(0..1)][nt(0..7)][e(0..1)]
    float    accB[32];   // layer-1 pre-act
    uint32_t h0f[16];    // A frags: [k(0..3)][q(0..3)]
    uint32_t h1f[16];
    #pragma unroll
    for (int i = 0; i < 16; ++i) { h0f[i] = 0u; h1f[i] = 0u; }

    // preload gather for step 0
    #pragma unroll
    for (int i = 0; i < 2; ++i) {
        int tok = g_tokT[rc[i]];  // step 0
        const float2* src = reinterpret_cast<const float2*>(g_embW0 + tok * 64) + tq;
        #pragma unroll
        for (int nt = 0; nt < 8; ++nt) {
            float2 v = src[nt * 4];
            accA[i * 16 + nt * 2]     = v.x;
            accA[i * 16 + nt * 2 + 1] = v.y;
        }
    }

    const float2* sB1f2 = reinterpret_cast<const float2*>(sB1);

    #pragma unroll 1
    for (int ts = 0; ts < SEQ; ++ts) {
        // tokens for next step (clamped; last-step extra gather is harmless)
        int tsn = (ts + 1 < SEQ) ? ts + 1 : SEQ - 1;
        int tkn[2];
        #pragma unroll
        for (int i = 0; i < 2; ++i) tkn[i] = g_tokT[tsn * B + rc[i]];

        // accB = b1
        #pragma unroll
        for (int nt = 0; nt < 8; ++nt) {
            float2 bv = sB1f2[nt * 4 + tq];
            accB[nt * 2]          = bv.x;
            accB[nt * 2 + 1]      = bv.y;
            accB[16 + nt * 2]     = bv.x;
            accB[16 + nt * 2 + 1] = bv.y;
        }

        // interleaved: accA += h0 @ Wh0 ; accB += h1 @ Wh1  (independent chains)
        #pragma unroll
        for (int kp = 0; kp < 2; ++kp) {
            #pragma unroll
            for (int nt = 0; nt < 8; ++nt) {
                uint32_t off = 2 * (nt * 8 * WSTRIDE + kp * 32);
                uint32_t x0, y0, z0, w0, x2, y2, z2, w2;
                ldsm4(x0, y0, z0, w0, aW0 + off);
                ldsm4(x2, y2, z2, w2, aW2 + off);
                mma16816(accA[nt*2], accA[nt*2+1], accA[16+nt*2], accA[16+nt*2+1],
                         h0f[(2*kp)*4+0], h0f[(2*kp)*4+1], h0f[(2*kp)*4+2], h0f[(2*kp)*4+3],
                         x0, y0);
                mma16816(accA[nt*2], accA[nt*2+1], accA[16+nt*2], accA[16+nt*2+1],
                         h0f[(2*kp+1)*4+0], h0f[(2*kp+1)*4+1], h0f[(2*kp+1)*4+2], h0f[(2*kp+1)*4+3],
                         z0, w0);
                mma16816(accB[nt*2], accB[nt*2+1], accB[16+nt*2], accB[16+nt*2+1],
                         h1f[(2*kp)*4+0], h1f[(2*kp)*4+1], h1f[(2*kp)*4+2], h1f[(2*kp)*4+3],
                         x2, y2);
                mma16816(accB[nt*2], accB[nt*2+1], accB[16+nt*2], accB[16+nt*2+1],
                         h1f[(2*kp+1)*4+0], h1f[(2*kp+1)*4+1], h1f[(2*kp+1)*4+2], h1f[(2*kp+1)*4+3],
                         z2, w2);
            }
        }

        // h0 = tanh(accA)  (pack fp32 pair -> bf16x2, then packed tanh)
        #pragma unroll
        for (int k = 0; k < 4; ++k) {
            h0f[k*4+0] = tanh_bf16x2(packbf(accA[4*k],      accA[4*k+1]));
            h0f[k*4+1] = tanh_bf16x2(packbf(accA[16+4*k],   accA[16+4*k+1]));
            h0f[k*4+2] = tanh_bf16x2(packbf(accA[4*k+2],    accA[4*k+3]));
            h0f[k*4+3] = tanh_bf16x2(packbf(accA[16+4*k+2], accA[16+4*k+3]));
        }

        // prefetch next-step gather into accA (covers L2 latency over layer 1)
        #pragma unroll
        for (int i = 0; i < 2; ++i) {
            const float2* src = reinterpret_cast<const float2*>(g_embW0 + tkn[i] * 64) + tq;
            #pragma unroll
            for (int nt = 0; nt < 8; ++nt) {
                float2 v = src[nt * 4];
                accA[i * 16 + nt * 2]     = v.x;
                accA[i * 16 + nt * 2 + 1] = v.y;
            }
        }

        // accB += h0new @ Wx1
        #pragma unroll
        for (int kp = 0; kp < 2; ++kp) {
            #pragma unroll
            for (int nt = 0; nt < 8; ++nt) {
                uint32_t off = 2 * (nt * 8 * WSTRIDE + kp * 32);
                uint32_t x1, y1, z1, w1;
                ldsm4(x1, y1, z1, w1, aW1 + off);
                mma16816(accB[nt*2], accB[nt*2+1], accB[16+nt*2], accB[16+nt*2+1],
                         h0f[(2*kp)*4+0], h0f[(2*kp)*4+1], h0f[(2*kp)*4+2], h0f[(2*kp)*4+3],
                         x1, y1);
                mma16816(accB[nt*2], accB[nt*2+1], accB[16+nt*2], accB[16+nt*2+1],
                         h0f[(2*kp+1)*4+0], h0f[(2*kp+1)*4+1], h0f[(2*kp+1)*4+2], h0f[(2*kp+1)*4+3],
                         z1, w1);
            }
        }

        // h1 = tanh(accB)
        #pragma unroll
        for (int k = 0; k < 4; ++k) {
            h1f[k*4+0] = tanh_bf16x2(packbf(accB[4*k],      accB[4*k+1]));
            h1f[k*4+1] = tanh_bf16x2(packbf(accB[16+4*k],   accB[16+4*k+1]));
            h1f[k*4+2] = tanh_bf16x2(packbf(accB[4*k+2],    accB[4*k+3]));
            h1f[k*4+3] = tanh_bf16x2(packbf(accB[16+4*k+2], accB[16+4*k+3]));
        }
    }

    // ---- head: sigmoid(tanh(accB) @ Wout + bout), fp32 tanh for the final step ----
    float wo[16];
    #pragma unroll
    for (int nt = 0; nt < 8; ++nt) {
        float2 v = *reinterpret_cast<const float2*>(Wout + nt * 8 + tq * 2);
        wo[nt * 2] = v.x; wo[nt * 2 + 1] = v.y;
    }
    float bo = bout[0];
    #pragma unroll
    for (int i = 0; i < 2; ++i) {
        float s = 0.f;
        #pragma unroll
        for (int nt = 0; nt < 8; ++nt) {
            s += fast_tanh(accB[i * 16 + nt * 2])     * wo[nt * 2];
            s += fast_tanh(accB[i * 16 + nt * 2 + 1]) * wo[nt * 2 + 1];
        }
        s += __shfl_xor_sync(0xffffffffu, s, 1);
        s += __shfl_xor_sync(0xffffffffu, s, 2);
        if (tq == 0 && rraw[i] < B)
            out[rraw[i]] = 1.0f / (1.0f + __expf(-(s + bo)));
    }
}

// ---------------------------------------------------------------------------
extern "C" void kernel_launch(void* const* d_in, const int* in_sizes, int n_in,
                              void* d_out, int out_size) {
    const int*   tokens = (const int*)  d_in[0];
    const float* emb    = (const float*)d_in[1];
    const float* Wx0    = (const float*)d_in[2];
    const float* Wh0    = (const float*)d_in[3];
    const float* b0     = (const float*)d_in[4];
    const float* Wx1    = (const float*)d_in[5];
    const float* Wh1    = (const float*)d_in[6];
    const float* b1     = (const float*)d_in[7];
    const float* Wout   = (const float*)d_in[8];
    const float* bout   = (const float*)d_in[9];
    float* out = (float*)d_out;

    int B = in_sizes[0] / SEQ;
    if (B > BMAX) B = BMAX;

    embw0_kernel<<<VOCAB / 16, 256>>>(emb, Wx0, b0);
    tok_transpose<<<(B + 255) / 256, 256>>>(tokens, B);

    int nblocks = (B + 63) / 64;
    rnn_kernel<<<nblocks, 128>>>(Wh0, Wx1, Wh1, b1, Wout, bout, out, B);
}